// round 5
// baseline (speedup 1.0000x reference)
#include <cuda_runtime.h>
#include <cstdint>
#include <math.h>

#define T_   384
#define B_   48
#define H_   256
#define G3   768
#define CSZ  8                 // CTAs per cluster
#define GB   3                 // batches per cluster
#define NCLU (B_/GB)           // 16 clusters
#define NCTA (NCLU*CSZ)        // 128 CTAs
#define THR  256

// ---------------- scratch (device globals; no runtime allocation) ----------------
__device__ float g_gi[(size_t)T_ * B_ * G3];
__device__ float g_ys0[(size_t)T_ * B_ * H_];
__device__ float g_skipc[B_];
__device__ float g_dcar[B_];

// ---------------- helpers ----------------
typedef unsigned long long ull;

__device__ __forceinline__ float sigm(float x) { return 1.f / (1.f + expf(-x)); }

__device__ __forceinline__ void fma2(ull& acc, ull a, ull b) {
    asm("fma.rn.f32x2 %0, %1, %2, %3;" : "=l"(acc) : "l"(a), "l"(b), "l"(acc));
}
__device__ __forceinline__ ull pack2(float lo, float hi) {
    ull r; asm("mov.b64 %0, {%1, %2};" : "=l"(r) : "f"(lo), "f"(hi)); return r;
}
__device__ __forceinline__ float2 unpack2(ull v) {
    float lo, hi; asm("mov.b64 {%0, %1}, %2;" : "=f"(lo), "=f"(hi) : "l"(v));
    return make_float2(lo, hi);
}

__device__ __forceinline__ void advance_state(float& u, float& d, float& s, float dn) {
    float bup = rintf(u);
    float nu  = (s > 0.f) ? fminf(fmaxf(u + d, 0.f), 1.f) * (1.f - bup) : dn * bup;
    d = (s > 0.f) ? d : dn;
    s = ((ceilf(0.5f / nu) - 1.f) > 0.f) ? 1.f : 0.f;
    u = nu;
}

__device__ __forceinline__ unsigned smem_u32(const void* p) {
    unsigned a;
    asm("{ .reg .u64 t; cvta.to.shared.u64 t, %1; cvt.u32.u64 %0, t; }" : "=r"(a) : "l"(p));
    return a;
}
__device__ __forceinline__ unsigned mapa_u32(unsigned a, unsigned r) {
    unsigned o; asm("mapa.shared::cluster.u32 %0, %1, %2;" : "=r"(o) : "r"(a), "r"(r)); return o;
}
__device__ __forceinline__ void st_clu(unsigned a, float v) {
    asm volatile("st.shared::cluster.f32 [%0], %1;" :: "r"(a), "f"(v) : "memory");
}
#define CLUSTER_SYNC() do { asm volatile("barrier.cluster.arrive.aligned;" ::: "memory"); \
                            asm volatile("barrier.cluster.wait.aligned;"   ::: "memory"); } while (0)

// ---------------- bulk gi GEMM: C[m][n] = sum_k A[m][k] * W[n][k] ----------------
__global__ void __launch_bounds__(128) gemm_xw(const float* __restrict__ x, int layer,
                                               const float* __restrict__ wih) {
    __shared__ float As[16][64];
    __shared__ float Bs[16][64];
    const float* A = layer ? (const float*)g_ys0 : x;
    const float* W = wih + (size_t)layer * G3 * H_;
    const int tid = threadIdx.x;
    const int m0 = blockIdx.x * 64, n0 = blockIdx.y * 64;
    const int tx = tid & 15, ty = tid >> 4;
    ull acc2[8][2];
#pragma unroll
    for (int i = 0; i < 8; i++) { acc2[i][0] = 0ull; acc2[i][1] = 0ull; }

    for (int kt = 0; kt < 256; kt += 16) {
#pragma unroll
        for (int i = 0; i < 2; i++) {
            int idx = tid + i * 128;
            int row = idx >> 2, k4 = idx & 3;
            float4 a = *(const float4*)&A[(size_t)(m0 + row) * 256 + kt + k4 * 4];
            As[k4*4+0][row] = a.x; As[k4*4+1][row] = a.y;
            As[k4*4+2][row] = a.z; As[k4*4+3][row] = a.w;
            float4 b = *(const float4*)&W[(size_t)(n0 + row) * 256 + kt + k4 * 4];
            Bs[k4*4+0][row] = b.x; Bs[k4*4+1][row] = b.y;
            Bs[k4*4+2][row] = b.z; Bs[k4*4+3][row] = b.w;
        }
        __syncthreads();
#pragma unroll
        for (int kk = 0; kk < 16; kk++) {
            float4 b4 = *(const float4*)&Bs[kk][tx * 4];
            ull b01 = pack2(b4.x, b4.y), b23 = pack2(b4.z, b4.w);
            float4 a0 = *(const float4*)&As[kk][ty * 8];
            float4 a1 = *(const float4*)&As[kk][ty * 8 + 4];
            float am[8] = {a0.x, a0.y, a0.z, a0.w, a1.x, a1.y, a1.z, a1.w};
#pragma unroll
            for (int i = 0; i < 8; i++) {
                ull am2 = pack2(am[i], am[i]);
                fma2(acc2[i][0], am2, b01);
                fma2(acc2[i][1], am2, b23);
            }
        }
        __syncthreads();
    }
#pragma unroll
    for (int i = 0; i < 8; i++) {
        float2 c01 = unpack2(acc2[i][0]), c23 = unpack2(acc2[i][1]);
        float4 o = make_float4(c01.x, c01.y, c23.x, c23.y);
        *(float4*)&g_gi[(size_t)(m0 + ty * 8 + i) * G3 + n0 + tx * 4] = o;
    }
}

// ---------------- clustered recurrence: one layer ----------------
__global__ void __launch_bounds__(THR, 1) __cluster_dims__(CSZ, 1, 1)
rec_kernel(int layer,
           const float* __restrict__ hiddens,   // [L][1][H]
           const float* __restrict__ whh,       // [L][768][256]
           const float* __restrict__ bih,       // [L][768]
           const float* __restrict__ bhh,       // [L][768]
           const float* __restrict__ lw,        // [L][1][H]
           const float* __restrict__ lb,        // [L][1]
           float* __restrict__ d_out)
{
    __shared__ float h_s[GB][H_];          // full h(t-1) for the cluster's 3 batches
    __shared__ float gh_s[32][3][GB];      // gate dots for this CTA's units
    __shared__ float parts_s[CSZ][GB];     // skip-gate partials from all ranks
    __shared__ float s_bu[GB], s_sk[GB];

    const int tid  = threadIdx.x;
    const int w    = tid >> 5;
    const int lane = tid & 31;
    unsigned rk; asm("mov.u32 %0, %%cluster_ctarank;" : "=r"(rk));
    const int cid = blockIdx.x / CSZ;
    const int bg0 = cid * GB;

    float* ys      = layer ? d_out : g_ys0;
    float* hs_out  = d_out + (size_t)T_ * B_ * H_ + (size_t)layer * B_ * H_;
    float* tu_out  = d_out + (size_t)T_ * B_ * H_ + 2 * B_ * H_;   // [B][2T]
    const float* gi  = g_gi;
    const float* h0  = hiddens + (size_t)layer * H_;
    const float* wh  = whh + (size_t)layer * G3 * H_;
    const float* bi  = bih + (size_t)layer * G3;
    const float* bh  = bhh + (size_t)layer * G3;
    const float* lwp = lw + (size_t)layer * H_;

    // ---- w_hh slices in registers (packed f32x2): 6 passes x 8 pairs ----
    const int r2 = lane >> 4, k16 = lane & 15;
    ull wv2[6][8];
    const float4* whp = (const float4*)wh;
#pragma unroll
    for (int p = 0; p < 6; p++) {
        int g = p >> 1, usub = (p & 1) * 2 + r2;
        int row = g * 256 + (int)rk * 32 + w * 4 + usub;
#pragma unroll
        for (int i = 0; i < 4; i++) {
            float4 v = whp[(size_t)row * 64 + k16 * 4 + i];
            wv2[p][i*2]   = pack2(v.x, v.y);
            wv2[p][i*2+1] = pack2(v.z, v.w);
        }
    }
    // epilogue constants (warps 0-2: lane -> (batch=w, unit=lane))
    const int eb = w, eu = lane, egu = (int)rk * 32 + eu;
    float bir = 0, biz = 0, bin = 0, bhr = 0, bhz = 0, bhn = 0, lwj = 0;
    if (w < 3) {
        bir = bi[egu]; biz = bi[256 + egu]; bin = bi[512 + egu];
        bhr = bh[egu]; bhz = bh[256 + egu]; bhn = bh[512 + egu];
        lwj = lwp[egu];
    }
    // skip-state (warp 3, lanes<GB; redundant per CTA, deterministic)
    float su = 1.f, sd = 0.f, ss = 0.f, lb_ = 0.f;
    if (w == 3 && lane < GB) {
        lb_ = lb[layer];
        if (layer) { sd = g_dcar[bg0 + lane]; ss = g_skipc[bg0 + lane]; }
    }
    // DSMEM peer addresses
    unsigned hb = smem_u32(h_s), pb = smem_u32(parts_s);
    unsigned peer_h[CSZ], peer_p[CSZ];
#pragma unroll
    for (int r = 0; r < CSZ; r++) { peer_h[r] = mapa_u32(hb, r); peer_p[r] = mapa_u32(pb, r); }

    // init h_s (each CTA holds the full h for its 3 batches)
    for (int i = tid; i < GB * H_; i += THR) ((float*)h_s)[i] = h0[i & (H_ - 1)];
    __syncthreads();
    CLUSTER_SYNC();

    // gi prefetch for t=0
    float gir = 0.f, giz = 0.f, gin = 0.f;
    if (w < 3) {
        const float* gp = gi + ((size_t)bg0 + eb) * G3 + egu;
        gir = gp[0]; giz = gp[256]; gin = gp[512];
    }

    for (int t = 0; t < T_; t++) {
        // skip-state update from step t-1 partials
        if (w == 3 && lane < GB) {
            if (t > 0) {
                float ps = 0.f;
#pragma unroll
                for (int r = 0; r < CSZ; r++) ps += parts_s[r][lane];
                advance_state(su, sd, ss, sigm(ps + lb_));
            }
            float bu = rintf(su);
            s_bu[lane] = bu; s_sk[lane] = ss;
            if (rk == 0) tu_out[(size_t)(bg0 + lane) * (2 * T_) + layer * T_ + t] = bu;
        }
        // load this lane's h k-slice once, reuse across all 6 passes (packed)
        ull h2[GB][8];
#pragma unroll
        for (int b = 0; b < GB; b++)
#pragma unroll
            for (int i = 0; i < 4; i++) {
                float4 v = *(const float4*)&h_s[b][k16 * 16 + i * 4];
                h2[b][i*2]   = pack2(v.x, v.y);
                h2[b][i*2+1] = pack2(v.z, v.w);
            }
        // GEMV: 6 passes, packed f32x2 FMAs (2 MAC/instr)
#pragma unroll
        for (int p = 0; p < 6; p++) {
            ull a20 = 0ull, a21 = 0ull, a22 = 0ull;
#pragma unroll
            for (int i = 0; i < 8; i++) {
                fma2(a20, wv2[p][i], h2[0][i]);
                fma2(a21, wv2[p][i], h2[1][i]);
                fma2(a22, wv2[p][i], h2[2][i]);
            }
            float2 f0 = unpack2(a20), f1 = unpack2(a21), f2 = unpack2(a22);
            float a0 = f0.x + f0.y, a1 = f1.x + f1.y, a2 = f2.x + f2.y;
#pragma unroll
            for (int m = 8; m >= 1; m >>= 1) {
                a0 += __shfl_xor_sync(0xffffffffu, a0, m);
                a1 += __shfl_xor_sync(0xffffffffu, a1, m);
                a2 += __shfl_xor_sync(0xffffffffu, a2, m);
            }
            if (k16 == 0) {
                int u = w * 4 + (p & 1) * 2 + r2, g = p >> 1;
                gh_s[u][g][0] = a0; gh_s[u][g][1] = a1; gh_s[u][g][2] = a2;
            }
        }
        __syncthreads();   // gh_s, s_bu, s_sk ready

        if (w < 3) {
            float ghr = gh_s[eu][0][eb], ghz = gh_s[eu][1][eb], ghn = gh_s[eu][2][eb];
            float bu = s_bu[eb], sk = s_sk[eb];
            float hprev = h_s[eb][egu];
            float r = sigm(gir + bir + ghr + bhr);
            float z = sigm(giz + biz + ghz + bhz);
            float n = tanhf(gin + bin + r * (ghn + bhn));
            float cand = (1.f - z) * n + z * hprev;
            float hns = cand * bu;
            float nh = (sk > 0.f) ? hprev * (1.f - bu) : hns;
            h_s[eb][egu] = nh;
            unsigned off = (unsigned)(eb * H_ + egu) * 4u;
#pragma unroll
            for (int r7 = 0; r7 < CSZ; r7++)
                if (r7 != (int)rk) st_clu(peer_h[r7] + off, nh);
            ys[((size_t)t * B_ + bg0 + eb) * H_ + egu] = nh;
            if (t == T_ - 1) hs_out[(size_t)(bg0 + eb) * H_ + egu] = nh;
            float pd = hns * lwj;
#pragma unroll
            for (int m = 16; m >= 1; m >>= 1) pd += __shfl_xor_sync(0xffffffffu, pd, m);
            if (lane == 0) {
                parts_s[rk][eb] = pd;
                unsigned poff = (unsigned)((int)rk * GB + eb) * 4u;
#pragma unroll
                for (int r7 = 0; r7 < CSZ; r7++)
                    if (r7 != (int)rk) st_clu(peer_p[r7] + poff, pd);
            }
            // prefetch gi for t+1 — hides L2/DRAM latency under the cluster barrier
            if (t + 1 < T_) {
                const float* gp = gi + ((size_t)(t + 1) * B_ + bg0 + eb) * G3 + egu;
                gir = gp[0]; giz = gp[256]; gin = gp[512];
            }
        }
        CLUSTER_SYNC();    // publish h slices + partials cluster-wide
    }

    // layer-0 final carry (skip, d) for layer 1
    if (layer == 0 && w == 3 && lane < GB && rk == 0) {
        float ps = 0.f;
#pragma unroll
        for (int r = 0; r < CSZ; r++) ps += parts_s[r][lane];
        advance_state(su, sd, ss, sigm(ps + lb_));
        g_dcar[bg0 + lane] = sd; g_skipc[bg0 + lane] = ss;
    }
}

// ---------------- launcher ----------------
extern "C" void kernel_launch(void* const* d_in, const int* in_sizes, int n_in,
                              void* d_out, int out_size) {
    const float* x   = (const float*)d_in[0];
    const float* hid = (const float*)d_in[1];
    const float* wih = (const float*)d_in[2];
    const float* whh = (const float*)d_in[3];
    const float* bih = (const float*)d_in[4];
    const float* bhh = (const float*)d_in[5];
    const float* lw  = (const float*)d_in[6];
    const float* lb  = (const float*)d_in[7];
    float* out = (float*)d_out;

    dim3 ggrid(T_ * B_ / 64, G3 / 64);   // (288, 12)
    gemm_xw<<<ggrid, 128>>>(x, 0, wih);
    rec_kernel<<<NCTA, THR>>>(0, hid, whh, bih, bhh, lw, lb, out);
    gemm_xw<<<ggrid, 128>>>(x, 1, wih);
    rec_kernel<<<NCTA, THR>>>(1, hid, whh, bih, bhh, lw, lb, out);
}